// round 2
// baseline (speedup 1.0000x reference)
#include <cuda_runtime.h>

// ---------------------------------------------------------------------------
// SNN loss, fused:  loss = -mean_i( log S_num(i) - log S_den(i) )
//   S_den(i) = sum_{j != i}              exp(-T * dist(i,j))
//   S_num(i) = sum_{j != i, y_j == y_i}  exp(-T * dist(i,j))
//   dist(i,j) = sqrt(max(||xi||^2 + ||xj||^2 - 2 xi.xj, 0))
// No max-shift needed: dist >= 0 -> exp in (0,1]; sums ~1e-16 >> fp32 denorm.
// ---------------------------------------------------------------------------

#define B_N   8192
#define D_K   1024
#define BM    128
#define BN    128
#define BK    16
#define NTHR  256
#define GRID_Y 16
#define JTILES (B_N / BN)              /* 64 */
#define JT_PER_BLOCK (JTILES / GRID_Y) /* 4  */

__device__ float g_xn[B_N];
__device__ float g_snum[B_N];
__device__ float g_sden[B_N];
__device__ int   g_lab[B_N];
__device__ float g_T;
__device__ int   g_y_is64;

__device__ __forceinline__ float fsqrt_approx(float v) {
    float r; asm("sqrt.approx.f32 %0, %1;" : "=f"(r) : "f"(v)); return r;
}
__device__ __forceinline__ float fexp2_approx(float v) {
    float r; asm("ex2.approx.f32 %0, %1;" : "=f"(r) : "f"(v)); return r;
}

// ---------------------------------------------------------------------------
// prep (single block): zero accumulators, parse T, detect y dtype.
// y dtype detection: labels are in [0,100). If y is int64, every odd 32-bit
// word of the buffer is a zero high-half. If int32, odd words are labels and
// at least one of 4096 of them is nonzero (probability of failure ~0).
// ---------------------------------------------------------------------------
__global__ void snn_prep(const void* __restrict__ Tin, const unsigned* __restrict__ yw) {
    __shared__ unsigned s_or[256];
    const int tid = threadIdx.x;

    for (int i = tid; i < B_N; i += 256) { g_snum[i] = 0.0f; g_sden[i] = 0.0f; }

    unsigned acc = 0;
    // scan odd words among the first 8192 words (safe for both layouts)
    for (int i = tid; i < B_N / 2; i += 256) acc |= yw[2 * i + 1];
    s_or[tid] = acc;
    __syncthreads();
    for (int s = 128; s > 0; s >>= 1) {
        if (tid < s) s_or[tid] |= s_or[tid + s];
        __syncthreads();
    }
    if (tid == 0) {
        g_y_is64 = (s_or[0] == 0u) ? 1 : 0;

        const unsigned* u = (const unsigned*)Tin;
        unsigned a = u[0];
        float T;
        if (a == 0x3F800000u) {
            T = 1.0f;                                   // float32 1.0
        } else if ((a & 0x7F800000u) >= 0x3F000000u && (a & 0x7F800000u) <= 0x43000000u) {
            T = __uint_as_float(a);                     // plausible float32
        } else if (a == 0u) {
            unsigned b = u[1];
            if (b != 0u) {                              // float64
                unsigned long long v = ((unsigned long long)b << 32) | a;
                T = (float)__longlong_as_double(v);
            } else {
                T = 0.0f;
            }
        } else {
            T = (float)(int)a;                          // small int32/int64
        }
        g_T = T;
    }
}

// ---------------------------------------------------------------------------
// normalize labels to int32 in g_lab
// ---------------------------------------------------------------------------
__global__ void snn_labels(const void* __restrict__ y) {
    int i = blockIdx.x * blockDim.x + threadIdx.x;
    if (i < B_N) {
        g_lab[i] = g_y_is64 ? (int)((const long long*)y)[i]
                            : ((const int*)y)[i];
    }
}

// ---------------------------------------------------------------------------
// row norms: one warp per row
// ---------------------------------------------------------------------------
__global__ __launch_bounds__(256) void snn_rownorm(const float* __restrict__ x) {
    int warp = threadIdx.x >> 5, lane = threadIdx.x & 31;
    int row  = blockIdx.x * 8 + warp;
    const float4* p = (const float4*)(x + (size_t)row * D_K);
    float s = 0.0f;
#pragma unroll
    for (int i = 0; i < 8; i++) {
        float4 v = p[i * 32 + lane];
        s += v.x * v.x + v.y * v.y + v.z * v.z + v.w * v.w;
    }
#pragma unroll
    for (int off = 16; off > 0; off >>= 1)
        s += __shfl_down_sync(0xFFFFFFFFu, s, off);
    if (lane == 0) g_xn[row] = s;
}

// ---------------------------------------------------------------------------
// main fused kernel: 128x128 Gram tile per block (8x8 per thread), K=1024 in
// 16-wide double-buffered smem tiles, fused sqrt/exp epilogue into per-row
// running sums, intra-warp reduction, one atomicAdd per row per block.
// ---------------------------------------------------------------------------
__global__ __launch_bounds__(NTHR) void snn_main(const float* __restrict__ x)
{
    __shared__ float As[2][BK][BM];
    __shared__ float Bs[2][BK][BN];
    __shared__ float s_xnj[BN];
    __shared__ int   s_labj[BN];

    const int tid  = threadIdx.x;
    const int tx   = tid & 15;
    const int ty   = tid >> 4;
    const int row0 = ty * 8;
    const int col0 = tx * 8;
    const int i0   = blockIdx.x * BM;

    float xni[8]; int labi[8];
#pragma unroll
    for (int r = 0; r < 8; r++) {
        xni[r]  = g_xn[i0 + row0 + r];
        labi[r] = g_lab[i0 + row0 + r];
    }

    float snum[8], sden[8];
#pragma unroll
    for (int r = 0; r < 8; r++) { snum[r] = 0.0f; sden[r] = 0.0f; }

    const float c0 = g_T * -1.4426950408889634f;   // exp(-T*d) = 2^(c0*d)

    // gmem->smem staging map: 512 float4 slots, 2 per thread (same row)
    const int slot0 = tid * 2;
    const int m0  = slot0 >> 2;
    const int kq0 = (slot0 & 3) * 4;
    const int m1  = (slot0 + 1) >> 2;
    const int kq1 = ((slot0 + 1) & 3) * 4;

#pragma unroll 1
    for (int q = 0; q < JT_PER_BLOCK; q++) {
        const int j0 = (blockIdx.y * JT_PER_BLOCK + q) * BN;

        __syncthreads();   // previous q's epilogue done before smem reuse
        if (tid < BN) {
            s_xnj[tid]  = g_xn[j0 + tid];
            s_labj[tid] = g_lab[j0 + tid];
        }

        float acc[8][8];
#pragma unroll
        for (int r = 0; r < 8; r++)
#pragma unroll
            for (int c = 0; c < 8; c++) acc[r][c] = 0.0f;

        // k-tile 0 -> buffer 0
        {
            float4 a0 = *(const float4*)&x[(size_t)(i0 + m0) * D_K + kq0];
            float4 a1 = *(const float4*)&x[(size_t)(i0 + m1) * D_K + kq1];
            float4 b0 = *(const float4*)&x[(size_t)(j0 + m0) * D_K + kq0];
            float4 b1 = *(const float4*)&x[(size_t)(j0 + m1) * D_K + kq1];
            As[0][kq0+0][m0]=a0.x; As[0][kq0+1][m0]=a0.y; As[0][kq0+2][m0]=a0.z; As[0][kq0+3][m0]=a0.w;
            As[0][kq1+0][m1]=a1.x; As[0][kq1+1][m1]=a1.y; As[0][kq1+2][m1]=a1.z; As[0][kq1+3][m1]=a1.w;
            Bs[0][kq0+0][m0]=b0.x; Bs[0][kq0+1][m0]=b0.y; Bs[0][kq0+2][m0]=b0.z; Bs[0][kq0+3][m0]=b0.w;
            Bs[0][kq1+0][m1]=b1.x; Bs[0][kq1+1][m1]=b1.y; Bs[0][kq1+2][m1]=b1.z; Bs[0][kq1+3][m1]=b1.w;
        }
        __syncthreads();

#pragma unroll 1
        for (int kt = 0; kt < D_K / BK; kt++) {
            const int buf = kt & 1;
            float4 a0, a1, b0, b1;
            const bool more = (kt < D_K / BK - 1);
            if (more) {
                const int kb = (kt + 1) * BK;
                a0 = *(const float4*)&x[(size_t)(i0 + m0) * D_K + kb + kq0];
                a1 = *(const float4*)&x[(size_t)(i0 + m1) * D_K + kb + kq1];
                b0 = *(const float4*)&x[(size_t)(j0 + m0) * D_K + kb + kq0];
                b1 = *(const float4*)&x[(size_t)(j0 + m1) * D_K + kb + kq1];
            }
#pragma unroll
            for (int k = 0; k < BK; k++) {
                float a[8], b[8];
                *(float4*)&a[0] = *(const float4*)&As[buf][k][row0];
                *(float4*)&a[4] = *(const float4*)&As[buf][k][row0 + 4];
                *(float4*)&b[0] = *(const float4*)&Bs[buf][k][col0];
                *(float4*)&b[4] = *(const float4*)&Bs[buf][k][col0 + 4];
#pragma unroll
                for (int r = 0; r < 8; r++)
#pragma unroll
                    for (int c = 0; c < 8; c++)
                        acc[r][c] = fmaf(a[r], b[c], acc[r][c]);
            }
            if (more) {
                const int nb = buf ^ 1;
                As[nb][kq0+0][m0]=a0.x; As[nb][kq0+1][m0]=a0.y; As[nb][kq0+2][m0]=a0.z; As[nb][kq0+3][m0]=a0.w;
                As[nb][kq1+0][m1]=a1.x; As[nb][kq1+1][m1]=a1.y; As[nb][kq1+2][m1]=a1.z; As[nb][kq1+3][m1]=a1.w;
                Bs[nb][kq0+0][m0]=b0.x; Bs[nb][kq0+1][m0]=b0.y; Bs[nb][kq0+2][m0]=b0.z; Bs[nb][kq0+3][m0]=b0.w;
                Bs[nb][kq1+0][m1]=b1.x; Bs[nb][kq1+1][m1]=b1.y; Bs[nb][kq1+2][m1]=b1.z; Bs[nb][kq1+3][m1]=b1.w;
                __syncthreads();
            }
        }

        // fused epilogue for this 128x128 tile
#pragma unroll
        for (int r = 0; r < 8; r++) {
            const int ig = i0 + row0 + r;
            float sn = 0.0f, sd = 0.0f;
#pragma unroll
            for (int c = 0; c < 8; c++) {
                const int jg = j0 + col0 + c;
                float d2 = fmaf(-2.0f, acc[r][c], xni[r] + s_xnj[col0 + c]);
                d2 = fmaxf(d2, 0.0f);
                float e = fexp2_approx(c0 * fsqrt_approx(d2));
                float ev = (jg != ig) ? e : 0.0f;
                sd += ev;
                sn += (s_labj[col0 + c] == labi[r]) ? ev : 0.0f;
            }
            sden[r] += sd;
            snum[r] += sn;
        }
    }

    // reduce across the 16 threads (tx) sharing each row, then one atomic/row
#pragma unroll
    for (int r = 0; r < 8; r++) {
        float sn = snum[r], sd = sden[r];
#pragma unroll
        for (int off = 8; off > 0; off >>= 1) {
            sn += __shfl_down_sync(0xFFFFFFFFu, sn, off, 16);
            sd += __shfl_down_sync(0xFFFFFFFFu, sd, off, 16);
        }
        if (tx == 0) {
            atomicAdd(&g_snum[i0 + row0 + r], sn);
            atomicAdd(&g_sden[i0 + row0 + r], sd);
        }
    }
}

// ---------------------------------------------------------------------------
// final: per-row logs + mean
// ---------------------------------------------------------------------------
__global__ void snn_final(float* __restrict__ out) {
    __shared__ float red[256];
    int tid = threadIdx.x;
    float local = 0.0f;
    for (int i = tid; i < B_N; i += 256) {
        float sn = g_snum[i], sd = g_sden[i];
        float num = (sn > 0.0f) ? logf(sn) : 0.0f;   // reference's -inf fixup
        float den = logf(sd);
        local += num - den;
    }
    red[tid] = local;
    __syncthreads();
    for (int s = 128; s > 0; s >>= 1) {
        if (tid < s) red[tid] += red[tid + s];
        __syncthreads();
    }
    if (tid == 0) out[0] = -red[0] / (float)B_N;
}

// ---------------------------------------------------------------------------
extern "C" void kernel_launch(void* const* d_in, const int* in_sizes, int n_in,
                              void* d_out, int out_size)
{
    const float* x  = (const float*)d_in[0];
    const void*  y  = d_in[1];
    const void*  Tp = d_in[2];
    (void)in_sizes; (void)n_in; (void)out_size;

    snn_prep<<<1, 256>>>(Tp, (const unsigned*)y);
    snn_labels<<<B_N / 256, 256>>>(y);
    snn_rownorm<<<B_N / 8, 256>>>(x);
    snn_main<<<dim3(B_N / BM, GRID_Y), NTHR>>>(x);
    snn_final<<<1, 256>>>((float*)d_out);
}

// round 4
// speedup vs baseline: 2.4896x; 2.4896x over previous
#include <cuda_runtime.h>
#include <cuda_bf16.h>
#include <cstdint>

// ---------------------------------------------------------------------------
// SNN loss via warp-level bf16 mma.sync Gram GEMM (hi/lo split folded into
// K-extension: A=[hi,hi,lo], B=[hi,lo,hi], K=3072 -> full-precision dot),
// fused sqrt/exp epilogue into per-row sums, then logs + mean.
// No sm_100a-gated instructions (no tcgen05): mma.sync + ldmatrix + cp.async.
// ---------------------------------------------------------------------------

#define B_N   8192
#define D_K   1024
#define KEXT  3072
#define BM    256
#define BN    128
#define BK    32
#define ITERS (KEXT / BK)   /* 96 */
#define NTHR  512
#define STRIDE 40           /* padded smem row: 32 data + 8 pad bf16 = 80B */
#define A_STAGE_BYTES (BM * STRIDE * 2)   /* 20480 */
#define B_STAGE_BYTES (BN * STRIDE * 2)   /* 10240 */
#define STAGE_SZ (A_STAGE_BYTES + B_STAGE_BYTES) /* 30720 */
#define SMEM_TOTAL (4 * STAGE_SZ + 1024)  /* 123904 */

__device__ float g_xn[B_N];
__device__ float g_snum[B_N];
__device__ float g_sden[B_N];
__device__ int   g_lab[B_N];
__device__ float g_T;
__device__ int   g_y_is64;
__device__ __nv_bfloat16 g_xa[(size_t)B_N * KEXT];   // rows: [hi, hi, lo]
__device__ __nv_bfloat16 g_xb[(size_t)B_N * KEXT];   // rows: [hi, lo, hi]

// ------------------------------- helpers -----------------------------------
__device__ __forceinline__ uint32_t smem_u32(const void* p) {
    uint32_t a;
    asm("{ .reg .u64 t; cvta.to.shared.u64 t, %1; cvt.u32.u64 %0, t; }"
        : "=r"(a) : "l"(p));
    return a;
}
__device__ __forceinline__ float fsqrt_approx(float v) {
    float r; asm("sqrt.approx.f32 %0, %1;" : "=f"(r) : "f"(v)); return r;
}
__device__ __forceinline__ float fexp2_approx(float v) {
    float r; asm("ex2.approx.f32 %0, %1;" : "=f"(r) : "f"(v)); return r;
}

#define LDSM_X4(r, addr) \
    asm volatile("ldmatrix.sync.aligned.m8n8.x4.shared.b16 {%0,%1,%2,%3}, [%4];" \
        : "=r"((r)[0]), "=r"((r)[1]), "=r"((r)[2]), "=r"((r)[3]) : "r"(addr))

__device__ __forceinline__ void mma_bf16(float* c, const uint32_t* a,
                                         uint32_t b0, uint32_t b1) {
    asm volatile(
        "mma.sync.aligned.m16n8k16.row.col.f32.bf16.bf16.f32 "
        "{%0,%1,%2,%3}, {%4,%5,%6,%7}, {%8,%9}, {%0,%1,%2,%3};"
        : "+f"(c[0]), "+f"(c[1]), "+f"(c[2]), "+f"(c[3])
        : "r"(a[0]), "r"(a[1]), "r"(a[2]), "r"(a[3]), "r"(b0), "r"(b1));
}

#define CP_ASYNC16(dst, src) \
    asm volatile("cp.async.cg.shared.global [%0], [%1], 16;" \
                 :: "r"(dst), "l"(src) : "memory")
#define CP_COMMIT() asm volatile("cp.async.commit_group;" ::: "memory")
#define CP_WAIT3()  asm volatile("cp.async.wait_group 3;" ::: "memory")

// ---------------------------------------------------------------------------
// setup kernels
// ---------------------------------------------------------------------------
__global__ void snn_prep(const void* __restrict__ Tin, const unsigned* __restrict__ yw) {
    __shared__ unsigned s_or[256];
    const int tid = threadIdx.x;
    for (int i = tid; i < B_N; i += 256) { g_snum[i] = 0.0f; g_sden[i] = 0.0f; }
    unsigned acc = 0;
    for (int i = tid; i < B_N / 2; i += 256) acc |= yw[2 * i + 1];
    s_or[tid] = acc;
    __syncthreads();
    for (int s = 128; s > 0; s >>= 1) { if (tid < s) s_or[tid] |= s_or[tid + s]; __syncthreads(); }
    if (tid == 0) {
        g_y_is64 = (s_or[0] == 0u) ? 1 : 0;
        const unsigned* u = (const unsigned*)Tin;
        unsigned a = u[0];
        float T;
        if (a == 0x3F800000u) T = 1.0f;
        else if ((a & 0x7F800000u) >= 0x3F000000u && (a & 0x7F800000u) <= 0x43000000u)
            T = __uint_as_float(a);
        else if (a == 0u) {
            unsigned b = u[1];
            T = b ? (float)__longlong_as_double(((unsigned long long)b << 32) | a) : 0.0f;
        } else T = (float)(int)a;
        g_T = T;
    }
}

__global__ void snn_labels(const void* __restrict__ y) {
    int i = blockIdx.x * blockDim.x + threadIdx.x;
    if (i < B_N)
        g_lab[i] = g_y_is64 ? (int)((const long long*)y)[i] : ((const int*)y)[i];
}

__global__ __launch_bounds__(256) void snn_rownorm(const float* __restrict__ x) {
    int warp = threadIdx.x >> 5, lane = threadIdx.x & 31;
    int row  = blockIdx.x * 8 + warp;
    const float4* p = (const float4*)(x + (size_t)row * D_K);
    float s = 0.0f;
#pragma unroll
    for (int i = 0; i < 8; i++) {
        float4 v = p[i * 32 + lane];
        s += v.x * v.x + v.y * v.y + v.z * v.z + v.w * v.w;
    }
#pragma unroll
    for (int off = 16; off > 0; off >>= 1) s += __shfl_down_sync(0xFFFFFFFFu, s, off);
    if (lane == 0) g_xn[row] = s;
}

__global__ __launch_bounds__(256) void snn_convert(const float* __restrict__ x) {
    int idx = blockIdx.x * 256 + threadIdx.x;    // float4 index
    int row = idx >> 8;                          // D_K/4 = 256 float4 per row
    int kq  = (idx & 255) * 4;
    float4 v = ((const float4*)x)[idx];
    __nv_bfloat16 h0 = __float2bfloat16(v.x), h1 = __float2bfloat16(v.y);
    __nv_bfloat16 h2 = __float2bfloat16(v.z), h3 = __float2bfloat16(v.w);
    __nv_bfloat16 l0 = __float2bfloat16(v.x - __bfloat162float(h0));
    __nv_bfloat16 l1 = __float2bfloat16(v.y - __bfloat162float(h1));
    __nv_bfloat16 l2 = __float2bfloat16(v.z - __bfloat162float(h2));
    __nv_bfloat16 l3 = __float2bfloat16(v.w - __bfloat162float(h3));
    __nv_bfloat162 hh01{h0, h1}, hh23{h2, h3}, ll01{l0, l1}, ll23{l2, l3};
    size_t base = (size_t)row * KEXT + kq;
    __nv_bfloat162* pa = (__nv_bfloat162*)(g_xa + base);
    __nv_bfloat162* pb = (__nv_bfloat162*)(g_xb + base);
    pa[0] = hh01; pa[1] = hh23;                       // A: hi at k
    pa[D_K/2] = hh01; pa[D_K/2 + 1] = hh23;           //    hi at k+1024
    pa[D_K]   = ll01; pa[D_K + 1]   = ll23;           //    lo at k+2048
    pb[0] = hh01; pb[1] = hh23;                       // B: hi at k
    pb[D_K/2] = ll01; pb[D_K/2 + 1] = ll23;           //    lo at k+1024
    pb[D_K]   = hh01; pb[D_K + 1]   = hh23;           //    hi at k+2048
}

// ---------------------------------------------------------------------------
// main GEMM + fused epilogue
// ---------------------------------------------------------------------------
__global__ __launch_bounds__(NTHR, 1) void snn_mma() {
    extern __shared__ __align__(16) char sm[];
    const uint32_t smb = smem_u32(sm);
    const int tid = threadIdx.x, wid = tid >> 5, lane = tid & 31;
    const int wM = wid >> 2, wN = wid & 3;      // 4x4 warp grid; warp tile 64x32
    const int i0 = blockIdx.x * BM, j0 = blockIdx.y * BN;

    float* s_xnj = (float*)(sm + 4 * STAGE_SZ);
    int*   s_labj = (int*)(sm + 4 * STAGE_SZ + 512);
    if (tid < BN) { s_xnj[tid] = g_xn[j0 + tid]; s_labj[tid] = g_lab[j0 + tid]; }

    // --- cp.async staging map: A 1024 16B-chunks (2/thread), B 512 (1/thread)
    const int ar0 = tid >> 2,          ac0 = tid & 3;
    const int ar1 = (tid + 512) >> 2;  // rows 128..255, same ac
    const int br  = tid >> 2,          bc = tid & 3;
    const __nv_bfloat16* gA0 = g_xa + (size_t)(i0 + ar0) * KEXT + ac0 * 8;
    const __nv_bfloat16* gA1 = g_xa + (size_t)(i0 + ar1) * KEXT + ac0 * 8;
    const __nv_bfloat16* gB  = g_xb + (size_t)(j0 + br ) * KEXT + bc  * 8;
    const uint32_t sa0 = (uint32_t)(ar0 * STRIDE + ac0 * 8) * 2;
    const uint32_t sa1 = (uint32_t)(ar1 * STRIDE + ac0 * 8) * 2;
    const uint32_t sb  = A_STAGE_BYTES + (uint32_t)(br * STRIDE + bc * 8) * 2;

    // --- ldmatrix per-lane offsets
    const int arl  = lane & 15;
    const int asel = (lane >> 4) & 1;
    const int brl  = (lane & 7) | ((lane >> 4) << 3);
    const int bsel = (lane >> 3) & 1;
    uint32_t aob[4], bob[2];
#pragma unroll
    for (int mi = 0; mi < 4; mi++)
        aob[mi] = (uint32_t)((wM * 64 + mi * 16 + arl) * STRIDE + asel * 8) * 2;
#pragma unroll
    for (int bi = 0; bi < 2; bi++)
        bob[bi] = A_STAGE_BYTES +
                  (uint32_t)((wN * 32 + bi * 16 + brl) * STRIDE + bsel * 8) * 2;

    float acc[4][4][4];
#pragma unroll
    for (int mi = 0; mi < 4; mi++)
#pragma unroll
        for (int ni = 0; ni < 4; ni++)
#pragma unroll
            for (int r = 0; r < 4; r++) acc[mi][ni][r] = 0.0f;

    // --- prologue: fill 4 stages
#pragma unroll
    for (int s = 0; s < 4; s++) {
        const uint32_t st = smb + s * STAGE_SZ;
        const size_t k0 = (size_t)s * BK;
        CP_ASYNC16(st + sa0, gA0 + k0);
        CP_ASYNC16(st + sa1, gA1 + k0);
        CP_ASYNC16(st + sb,  gB  + k0);
        CP_COMMIT();
    }
    CP_WAIT3();
    __syncthreads();

    // --- mainloop
#pragma unroll 1
    for (int kt = 0; kt < ITERS; kt++) {
        const uint32_t st = smb + (kt & 3) * STAGE_SZ;
#pragma unroll
        for (int ks = 0; ks < 2; ks++) {
            uint32_t a[4][4], b[2][4];
#pragma unroll
            for (int mi = 0; mi < 4; mi++) LDSM_X4(a[mi], st + aob[mi] + ks * 32);
#pragma unroll
            for (int bi = 0; bi < 2; bi++) LDSM_X4(b[bi], st + bob[bi] + ks * 32);
#pragma unroll
            for (int mi = 0; mi < 4; mi++)
#pragma unroll
                for (int ni = 0; ni < 4; ni++)
                    mma_bf16(acc[mi][ni], a[mi],
                             b[ni >> 1][(ni & 1) * 2], b[ni >> 1][(ni & 1) * 2 + 1]);
        }
        __syncthreads();
        if (kt + 4 < ITERS) {
            const uint32_t sn = smb + (kt & 3) * STAGE_SZ;
            const size_t k0 = (size_t)(kt + 4) * BK;
            CP_ASYNC16(sn + sa0, gA0 + k0);
            CP_ASYNC16(sn + sa1, gA1 + k0);
            CP_ASYNC16(sn + sb,  gB  + k0);
        }
        CP_COMMIT();
        CP_WAIT3();
        __syncthreads();
    }

    // --- fused epilogue
    const float c0 = g_T * -1.4426950408889634f;
#pragma unroll
    for (int mi = 0; mi < 4; mi++) {
#pragma unroll
        for (int h = 0; h < 2; h++) {
            const int rowl = wM * 64 + mi * 16 + (lane >> 2) + h * 8;
            const int ig = i0 + rowl;
            const float xni = g_xn[ig];
            const int labi = g_lab[ig];
            float sd = 0.0f, sn = 0.0f;
#pragma unroll
            for (int ni = 0; ni < 4; ni++) {
#pragma unroll
                for (int e = 0; e < 2; e++) {
                    const int cl = wN * 32 + ni * 8 + (lane & 3) * 2 + e;
                    float dot = acc[mi][ni][h * 2 + e];
                    float d2 = fmaf(-2.0f, dot, xni + s_xnj[cl]);
                    d2 = fmaxf(d2, 0.0f);
                    float ev = fexp2_approx(c0 * fsqrt_approx(d2));
                    if (j0 + cl == ig) ev = 0.0f;
                    sd += ev;
                    sn += (s_labj[cl] == labi) ? ev : 0.0f;
                }
            }
            sd += __shfl_xor_sync(0xFFFFFFFFu, sd, 1);
            sd += __shfl_xor_sync(0xFFFFFFFFu, sd, 2);
            sn += __shfl_xor_sync(0xFFFFFFFFu, sn, 1);
            sn += __shfl_xor_sync(0xFFFFFFFFu, sn, 2);
            if ((lane & 3) == 0) {
                atomicAdd(&g_sden[ig], sd);
                atomicAdd(&g_snum[ig], sn);
            }
        }
    }
}

// ---------------------------------------------------------------------------
// final reduction
// ---------------------------------------------------------------------------
__global__ void snn_final(float* __restrict__ out) {
    __shared__ float red[256];
    int tid = threadIdx.x;
    float local = 0.0f;
    for (int i = tid; i < B_N; i += 256) {
        float sn = g_snum[i], sd = g_sden[i];
        float num = (sn > 0.0f) ? logf(sn) : 0.0f;
        float den = logf(sd);
        local += num - den;
    }
    red[tid] = local;
    __syncthreads();
    for (int s = 128; s > 0; s >>= 1) { if (tid < s) red[tid] += red[tid + s]; __syncthreads(); }
    if (tid == 0) out[0] = -red[0] / (float)B_N;
}

// ---------------------------------------------------------------------------
extern "C" void kernel_launch(void* const* d_in, const int* in_sizes, int n_in,
                              void* d_out, int out_size)
{
    const float* x  = (const float*)d_in[0];
    const void*  y  = d_in[1];
    const void*  Tp = d_in[2];
    (void)in_sizes; (void)n_in; (void)out_size;

    cudaFuncSetAttribute(snn_mma, cudaFuncAttributeMaxDynamicSharedMemorySize, SMEM_TOTAL);

    snn_prep<<<1, 256>>>(Tp, (const unsigned*)y);
    snn_labels<<<B_N / 256, 256>>>(y);
    snn_rownorm<<<B_N / 8, 256>>>(x);
    snn_convert<<<(B_N * D_K / 4) / 256, 256>>>(x);
    snn_mma<<<dim3(B_N / BM, B_N / BN), NTHR, SMEM_TOTAL>>>();
    snn_final<<<1, 256>>>((float*)d_out);
}

// round 5
// speedup vs baseline: 2.6213x; 1.0529x over previous
#include <cuda_runtime.h>
#include <cuda_bf16.h>
#include <cstdint>

// ---------------------------------------------------------------------------
// SNN loss via warp-level bf16 mma.sync Gram GEMM.
// Split x = hi + lo (bf16 each); dot = hi.hi + hi.lo + lo.hi (drop lo.lo).
// This round: separate hi/lo tiles (3 MMA passes per K-chunk, 33% less
// traffic than K-extension), 8 warps x (64x64) warp tiles (MMA-bound, not
// LDSM-bound), 3-stage cp.async pipeline with one sync per iteration.
// ---------------------------------------------------------------------------

#define B_N   8192
#define D_K   1024
#define BM    256
#define BN    128
#define BK    32
#define ITERS (D_K / BK)    /* 32 */
#define NTHR  256
#define NSTAGE 3
#define STRIDE 40           /* padded smem row: 32 data + 8 pad bf16 = 80B */

#define T_AHI 0
#define T_ALO (BM * STRIDE * 2)                 /* 20480 */
#define T_BHI (2 * BM * STRIDE * 2)             /* 40960 */
#define T_BLO (2 * BM * STRIDE * 2 + BN * STRIDE * 2) /* 51200 */
#define STAGE_SZ (2 * (BM + BN) * STRIDE * 2)   /* 61440 */
#define SMEM_TOTAL (NSTAGE * STAGE_SZ + 1024)   /* 185344 */

__device__ float g_xn[B_N];
__device__ float g_snum[B_N];
__device__ float g_sden[B_N];
__device__ int   g_lab[B_N];
__device__ float g_T;
__device__ int   g_y_is64;
__device__ __nv_bfloat16 g_xhi[(size_t)B_N * D_K];
__device__ __nv_bfloat16 g_xlo[(size_t)B_N * D_K];

// ------------------------------- helpers -----------------------------------
__device__ __forceinline__ uint32_t smem_u32(const void* p) {
    uint32_t a;
    asm("{ .reg .u64 t; cvta.to.shared.u64 t, %1; cvt.u32.u64 %0, t; }"
        : "=r"(a) : "l"(p));
    return a;
}
__device__ __forceinline__ float fsqrt_approx(float v) {
    float r; asm("sqrt.approx.f32 %0, %1;" : "=f"(r) : "f"(v)); return r;
}
__device__ __forceinline__ float fexp2_approx(float v) {
    float r; asm("ex2.approx.f32 %0, %1;" : "=f"(r) : "f"(v)); return r;
}

#define LDSM_X4(r, addr) \
    asm volatile("ldmatrix.sync.aligned.m8n8.x4.shared.b16 {%0,%1,%2,%3}, [%4];" \
        : "=r"((r)[0]), "=r"((r)[1]), "=r"((r)[2]), "=r"((r)[3]) : "r"(addr))

__device__ __forceinline__ void mma_bf16(float* c, const uint32_t* a,
                                         uint32_t b0, uint32_t b1) {
    asm volatile(
        "mma.sync.aligned.m16n8k16.row.col.f32.bf16.bf16.f32 "
        "{%0,%1,%2,%3}, {%4,%5,%6,%7}, {%8,%9}, {%0,%1,%2,%3};"
        : "+f"(c[0]), "+f"(c[1]), "+f"(c[2]), "+f"(c[3])
        : "r"(a[0]), "r"(a[1]), "r"(a[2]), "r"(a[3]), "r"(b0), "r"(b1));
}

#define CP_ASYNC16(dst, src) \
    asm volatile("cp.async.cg.shared.global [%0], [%1], 16;" \
                 :: "r"(dst), "l"(src) : "memory")
#define CP_COMMIT() asm volatile("cp.async.commit_group;" ::: "memory")
#define CP_WAIT1()  asm volatile("cp.async.wait_group 1;" ::: "memory")

// ---------------------------------------------------------------------------
// setup kernels
// ---------------------------------------------------------------------------
__global__ void snn_prep(const void* __restrict__ Tin, const unsigned* __restrict__ yw) {
    __shared__ unsigned s_or[256];
    const int tid = threadIdx.x;
    for (int i = tid; i < B_N; i += 256) { g_snum[i] = 0.0f; g_sden[i] = 0.0f; }
    unsigned acc = 0;
    for (int i = tid; i < B_N / 2; i += 256) acc |= yw[2 * i + 1];
    s_or[tid] = acc;
    __syncthreads();
    for (int s = 128; s > 0; s >>= 1) { if (tid < s) s_or[tid] |= s_or[tid + s]; __syncthreads(); }
    if (tid == 0) {
        g_y_is64 = (s_or[0] == 0u) ? 1 : 0;
        const unsigned* u = (const unsigned*)Tin;
        unsigned a = u[0];
        float T;
        if (a == 0x3F800000u) T = 1.0f;
        else if ((a & 0x7F800000u) >= 0x3F000000u && (a & 0x7F800000u) <= 0x43000000u)
            T = __uint_as_float(a);
        else if (a == 0u) {
            unsigned b = u[1];
            T = b ? (float)__longlong_as_double(((unsigned long long)b << 32) | a) : 0.0f;
        } else T = (float)(int)a;
        g_T = T;
    }
}

__global__ void snn_labels(const void* __restrict__ y) {
    int i = blockIdx.x * blockDim.x + threadIdx.x;
    if (i < B_N)
        g_lab[i] = g_y_is64 ? (int)((const long long*)y)[i] : ((const int*)y)[i];
}

__global__ __launch_bounds__(256) void snn_rownorm(const float* __restrict__ x) {
    int warp = threadIdx.x >> 5, lane = threadIdx.x & 31;
    int row  = blockIdx.x * 8 + warp;
    const float4* p = (const float4*)(x + (size_t)row * D_K);
    float s = 0.0f;
#pragma unroll
    for (int i = 0; i < 8; i++) {
        float4 v = p[i * 32 + lane];
        s += v.x * v.x + v.y * v.y + v.z * v.z + v.w * v.w;
    }
#pragma unroll
    for (int off = 16; off > 0; off >>= 1) s += __shfl_down_sync(0xFFFFFFFFu, s, off);
    if (lane == 0) g_xn[row] = s;
}

__global__ __launch_bounds__(256) void snn_convert(const float* __restrict__ x) {
    int idx = blockIdx.x * 256 + threadIdx.x;    // float4 index
    float4 v = ((const float4*)x)[idx];
    __nv_bfloat16 h0 = __float2bfloat16(v.x), h1 = __float2bfloat16(v.y);
    __nv_bfloat16 h2 = __float2bfloat16(v.z), h3 = __float2bfloat16(v.w);
    __nv_bfloat16 l0 = __float2bfloat16(v.x - __bfloat162float(h0));
    __nv_bfloat16 l1 = __float2bfloat16(v.y - __bfloat162float(h1));
    __nv_bfloat16 l2 = __float2bfloat16(v.z - __bfloat162float(h2));
    __nv_bfloat16 l3 = __float2bfloat16(v.w - __bfloat162float(h3));
    __nv_bfloat162* ph = (__nv_bfloat162*)(g_xhi + (size_t)idx * 4);
    __nv_bfloat162* pl = (__nv_bfloat162*)(g_xlo + (size_t)idx * 4);
    ph[0] = __nv_bfloat162{h0, h1}; ph[1] = __nv_bfloat162{h2, h3};
    pl[0] = __nv_bfloat162{l0, l1}; pl[1] = __nv_bfloat162{l2, l3};
}

// ---------------------------------------------------------------------------
// main GEMM + fused epilogue
// ---------------------------------------------------------------------------
__device__ __forceinline__ void stage_load(uint32_t st, int i0, int j0, int k0, int tid) {
    const int rA = tid >> 2;             // 0..63
    const int cb = (tid & 3) * 8;        // bf16 col within chunk
    const size_t kc = (size_t)k0 + cb;
#pragma unroll
    for (int r = 0; r < 4; r++) {
        const int row = rA + 64 * r;
        const uint32_t so = (uint32_t)(row * STRIDE + cb) * 2;
        CP_ASYNC16(st + T_AHI + so, g_xhi + (size_t)(i0 + row) * D_K + kc);
        CP_ASYNC16(st + T_ALO + so, g_xlo + (size_t)(i0 + row) * D_K + kc);
    }
#pragma unroll
    for (int r = 0; r < 2; r++) {
        const int row = rA + 64 * r;
        const uint32_t so = (uint32_t)(row * STRIDE + cb) * 2;
        CP_ASYNC16(st + T_BHI + so, g_xhi + (size_t)(j0 + row) * D_K + kc);
        CP_ASYNC16(st + T_BLO + so, g_xlo + (size_t)(j0 + row) * D_K + kc);
    }
}

__global__ __launch_bounds__(NTHR, 1) void snn_mma() {
    extern __shared__ __align__(16) char sm[];
    const uint32_t smb = smem_u32(sm);
    const int tid = threadIdx.x, wid = tid >> 5, lane = tid & 31;
    const int wM = wid >> 1, wN = wid & 1;      // 4x2 warp grid; warp tile 64x64
    const int i0 = blockIdx.x * BM, j0 = blockIdx.y * BN;

    float* s_xnj  = (float*)(sm + NSTAGE * STAGE_SZ);
    int*   s_labj = (int*)(sm + NSTAGE * STAGE_SZ + 512);
    if (tid < BN) { s_xnj[tid] = g_xn[j0 + tid]; s_labj[tid] = g_lab[j0 + tid]; }

    // ldmatrix per-lane offsets
    const int arl  = lane & 15;
    const int asel = (lane >> 4) & 1;
    const int brl  = (lane & 7) | ((lane >> 4) << 3);
    const int bsel = (lane >> 3) & 1;
    uint32_t aob[4], bob[4];
#pragma unroll
    for (int mi = 0; mi < 4; mi++)
        aob[mi] = (uint32_t)((wM * 64 + mi * 16 + arl) * STRIDE + asel * 8) * 2;
#pragma unroll
    for (int bi = 0; bi < 4; bi++)
        bob[bi] = (uint32_t)((wN * 64 + bi * 16 + brl) * STRIDE + bsel * 8) * 2;

    float acc[4][8][4];
#pragma unroll
    for (int mi = 0; mi < 4; mi++)
#pragma unroll
        for (int ni = 0; ni < 8; ni++)
#pragma unroll
            for (int r = 0; r < 4; r++) acc[mi][ni][r] = 0.0f;

    // prologue: stages 0 and 1
    stage_load(smb + 0 * STAGE_SZ, i0, j0, 0, tid);
    CP_COMMIT();
    stage_load(smb + 1 * STAGE_SZ, i0, j0, BK, tid);
    CP_COMMIT();

#pragma unroll 1
    for (int kt = 0; kt < ITERS; kt++) {
        CP_WAIT1();
        __syncthreads();
        if (kt + 2 < ITERS)
            stage_load(smb + ((kt + 2) % NSTAGE) * STAGE_SZ, i0, j0, (kt + 2) * BK, tid);
        CP_COMMIT();

        const uint32_t st = smb + (kt % NSTAGE) * STAGE_SZ;
#pragma unroll
        for (int ks = 0; ks < 2; ks++) {
            uint32_t ah[4][4], bh[4][4], t[4][4];
#pragma unroll
            for (int mi = 0; mi < 4; mi++) LDSM_X4(ah[mi], st + T_AHI + aob[mi] + ks * 32);
#pragma unroll
            for (int bi = 0; bi < 4; bi++) LDSM_X4(bh[bi], st + T_BHI + bob[bi] + ks * 32);
#pragma unroll
            for (int mi = 0; mi < 4; mi++)
#pragma unroll
                for (int ni = 0; ni < 8; ni++)
                    mma_bf16(acc[mi][ni], ah[mi],
                             bh[ni >> 1][(ni & 1) * 2], bh[ni >> 1][(ni & 1) * 2 + 1]);
            // hi_i . lo_j
#pragma unroll
            for (int bi = 0; bi < 4; bi++) LDSM_X4(t[bi], st + T_BLO + bob[bi] + ks * 32);
#pragma unroll
            for (int mi = 0; mi < 4; mi++)
#pragma unroll
                for (int ni = 0; ni < 8; ni++)
                    mma_bf16(acc[mi][ni], ah[mi],
                             t[ni >> 1][(ni & 1) * 2], t[ni >> 1][(ni & 1) * 2 + 1]);
            // lo_i . hi_j
#pragma unroll
            for (int mi = 0; mi < 4; mi++) LDSM_X4(t[mi], st + T_ALO + aob[mi] + ks * 32);
#pragma unroll
            for (int mi = 0; mi < 4; mi++)
#pragma unroll
                for (int ni = 0; ni < 8; ni++)
                    mma_bf16(acc[mi][ni], t[mi],
                             bh[ni >> 1][(ni & 1) * 2], bh[ni >> 1][(ni & 1) * 2 + 1]);
        }
    }

    // --- fused epilogue
    const float c0 = g_T * -1.4426950408889634f;
#pragma unroll
    for (int mi = 0; mi < 4; mi++) {
#pragma unroll
        for (int h = 0; h < 2; h++) {
            const int rowl = wM * 64 + mi * 16 + (lane >> 2) + h * 8;
            const int ig = i0 + rowl;
            const float xni = g_xn[ig];
            const int labi = g_lab[ig];
            float sd = 0.0f, sn = 0.0f;
#pragma unroll
            for (int ni = 0; ni < 8; ni++) {
#pragma unroll
                for (int e = 0; e < 2; e++) {
                    const int cl = wN * 64 + ni * 8 + (lane & 3) * 2 + e;
                    float dot = acc[mi][ni][h * 2 + e];
                    float d2 = fmaf(-2.0f, dot, xni + s_xnj[cl]);
                    d2 = fmaxf(d2, 0.0f);
                    float ev = fexp2_approx(c0 * fsqrt_approx(d2));
                    if (j0 + cl == ig) ev = 0.0f;
                    sd += ev;
                    sn += (s_labj[cl] == labi) ? ev : 0.0f;
                }
            }
            sd += __shfl_xor_sync(0xFFFFFFFFu, sd, 1);
            sd += __shfl_xor_sync(0xFFFFFFFFu, sd, 2);
            sn += __shfl_xor_sync(0xFFFFFFFFu, sn, 1);
            sn += __shfl_xor_sync(0xFFFFFFFFu, sn, 2);
            if ((lane & 3) == 0) {
                atomicAdd(&g_sden[ig], sd);
                atomicAdd(&g_snum[ig], sn);
            }
        }
    }
}

// ---------------------------------------------------------------------------
// final reduction
// ---------------------------------------------------------------------------
__global__ void snn_final(float* __restrict__ out) {
    __shared__ float red[256];
    int tid = threadIdx.x;
    float local = 0.0f;
    for (int i = tid; i < B_N; i += 256) {
        float sn = g_snum[i], sd = g_sden[i];
        float num = (sn > 0.0f) ? logf(sn) : 0.0f;
        float den = logf(sd);
        local += num - den;
    }
    red[tid] = local;
    __syncthreads();
    for (int s = 128; s > 0; s >>= 1) { if (tid < s) red[tid] += red[tid + s]; __syncthreads(); }
    if (tid == 0) out[0] = -red[0] / (float)B_N;
}

// ---------------------------------------------------------------------------
extern "C" void kernel_launch(void* const* d_in, const int* in_sizes, int n_in,
                              void* d_out, int out_size)
{
    const float* x  = (const float*)d_in[0];
    const void*  y  = d_in[1];
    const void*  Tp = d_in[2];
    (void)in_sizes; (void)n_in; (void)out_size;

    cudaFuncSetAttribute(snn_mma, cudaFuncAttributeMaxDynamicSharedMemorySize, SMEM_TOTAL);

    snn_prep<<<1, 256>>>(Tp, (const unsigned*)y);
    snn_labels<<<B_N / 256, 256>>>(y);
    snn_rownorm<<<B_N / 8, 256>>>(x);
    snn_convert<<<(B_N * D_K / 4) / 256, 256>>>(x);
    snn_mma<<<dim3(B_N / BM, B_N / BN), NTHR, SMEM_TOTAL>>>();
    snn_final<<<1, 256>>>((float*)d_out);
}

// round 6
// speedup vs baseline: 9.1295x; 3.4828x over previous
#include <cuda_runtime.h>
#include <cuda_bf16.h>
#include <cstdint>

// ---------------------------------------------------------------------------
// SNN loss via bf16 mma.sync Gram GEMM, single pass (pure bf16 dot; xn in
// fp32 keeps the dropped rounding terms zero-mean -> final error ~1e-5),
// symmetric schedule: only tiles (I,J) with J >= 2I are computed.
//   J in {2I, 2I+1}: tile pair covers the 256x256 diagonal block's ordered
//     pairs exactly once -> row accumulation only.
//   J >= 2I+2: strictly upper triangle -> row accumulation (pairs (i,j))
//     AND column accumulation (mirrored pairs (j,i)), e and label symmetric.
// ---------------------------------------------------------------------------

#define B_N   8192
#define D_K   1024
#define BM    256
#define BN    128
#define BK    32
#define ITERS (D_K / BK)    /* 32 */
#define NTHR  256
#define NSTAGE 3
#define STRIDE 40           /* padded smem row: 32 data + 8 pad bf16 = 80B */

#define T_A 0
#define T_B (BM * STRIDE * 2)                  /* 20480 */
#define STAGE_SZ ((BM + BN) * STRIDE * 2)      /* 30720 */
#define SMEM_TOTAL (NSTAGE * STAGE_SZ + 1024)  /* 93184 */
#define NTILES 1056                            /* sum_{I=0}^{31} (64-2I) */

__device__ float g_xn[B_N];
__device__ float g_snum[B_N];
__device__ float g_sden[B_N];
__device__ int   g_lab[B_N];
__device__ float g_T;
__device__ int   g_y_is64;
__device__ __nv_bfloat16 g_xb[(size_t)B_N * D_K];

// ------------------------------- helpers -----------------------------------
__device__ __forceinline__ uint32_t smem_u32(const void* p) {
    uint32_t a;
    asm("{ .reg .u64 t; cvta.to.shared.u64 t, %1; cvt.u32.u64 %0, t; }"
        : "=r"(a) : "l"(p));
    return a;
}
__device__ __forceinline__ float fsqrt_approx(float v) {
    float r; asm("sqrt.approx.f32 %0, %1;" : "=f"(r) : "f"(v)); return r;
}
__device__ __forceinline__ float fexp2_approx(float v) {
    float r; asm("ex2.approx.f32 %0, %1;" : "=f"(r) : "f"(v)); return r;
}

#define LDSM_X4(r, addr) \
    asm volatile("ldmatrix.sync.aligned.m8n8.x4.shared.b16 {%0,%1,%2,%3}, [%4];" \
        : "=r"((r)[0]), "=r"((r)[1]), "=r"((r)[2]), "=r"((r)[3]) : "r"(addr))

__device__ __forceinline__ void mma_bf16(float* c, const uint32_t* a,
                                         uint32_t b0, uint32_t b1) {
    asm volatile(
        "mma.sync.aligned.m16n8k16.row.col.f32.bf16.bf16.f32 "
        "{%0,%1,%2,%3}, {%4,%5,%6,%7}, {%8,%9}, {%0,%1,%2,%3};"
        : "+f"(c[0]), "+f"(c[1]), "+f"(c[2]), "+f"(c[3])
        : "r"(a[0]), "r"(a[1]), "r"(a[2]), "r"(a[3]), "r"(b0), "r"(b1));
}

#define CP_ASYNC16(dst, src) \
    asm volatile("cp.async.cg.shared.global [%0], [%1], 16;" \
                 :: "r"(dst), "l"(src) : "memory")
#define CP_COMMIT() asm volatile("cp.async.commit_group;" ::: "memory")
#define CP_WAIT1()  asm volatile("cp.async.wait_group 1;" ::: "memory")

// ---------------------------------------------------------------------------
// setup kernels
// ---------------------------------------------------------------------------
__global__ void snn_prep(const void* __restrict__ Tin, const unsigned* __restrict__ yw) {
    __shared__ unsigned s_or[256];
    const int tid = threadIdx.x;
    for (int i = tid; i < B_N; i += 256) { g_snum[i] = 0.0f; g_sden[i] = 0.0f; }
    unsigned acc = 0;
    for (int i = tid; i < B_N / 2; i += 256) acc |= yw[2 * i + 1];
    s_or[tid] = acc;
    __syncthreads();
    for (int s = 128; s > 0; s >>= 1) { if (tid < s) s_or[tid] |= s_or[tid + s]; __syncthreads(); }
    if (tid == 0) {
        g_y_is64 = (s_or[0] == 0u) ? 1 : 0;
        const unsigned* u = (const unsigned*)Tin;
        unsigned a = u[0];
        float T;
        if (a == 0x3F800000u) T = 1.0f;
        else if ((a & 0x7F800000u) >= 0x3F000000u && (a & 0x7F800000u) <= 0x43000000u)
            T = __uint_as_float(a);
        else if (a == 0u) {
            unsigned b = u[1];
            T = b ? (float)__longlong_as_double(((unsigned long long)b << 32) | a) : 0.0f;
        } else T = (float)(int)a;
        g_T = T;
    }
}

__global__ void snn_labels(const void* __restrict__ y) {
    int i = blockIdx.x * blockDim.x + threadIdx.x;
    if (i < B_N)
        g_lab[i] = g_y_is64 ? (int)((const long long*)y)[i] : ((const int*)y)[i];
}

__global__ __launch_bounds__(256) void snn_rownorm(const float* __restrict__ x) {
    int warp = threadIdx.x >> 5, lane = threadIdx.x & 31;
    int row  = blockIdx.x * 8 + warp;
    const float4* p = (const float4*)(x + (size_t)row * D_K);
    float s = 0.0f;
#pragma unroll
    for (int i = 0; i < 8; i++) {
        float4 v = p[i * 32 + lane];
        s += v.x * v.x + v.y * v.y + v.z * v.z + v.w * v.w;
    }
#pragma unroll
    for (int off = 16; off > 0; off >>= 1) s += __shfl_down_sync(0xFFFFFFFFu, s, off);
    if (lane == 0) g_xn[row] = s;
}

__global__ __launch_bounds__(256) void snn_convert(const float* __restrict__ x) {
    int idx = blockIdx.x * 256 + threadIdx.x;    // 8 floats per thread
    float4 v0 = ((const float4*)x)[idx * 2];
    float4 v1 = ((const float4*)x)[idx * 2 + 1];
    __nv_bfloat162 o[4];
    o[0] = __nv_bfloat162{__float2bfloat16(v0.x), __float2bfloat16(v0.y)};
    o[1] = __nv_bfloat162{__float2bfloat16(v0.z), __float2bfloat16(v0.w)};
    o[2] = __nv_bfloat162{__float2bfloat16(v1.x), __float2bfloat16(v1.y)};
    o[3] = __nv_bfloat162{__float2bfloat16(v1.z), __float2bfloat16(v1.w)};
    *(float4*)(g_xb + (size_t)idx * 8) = *(float4*)o;
}

// ---------------------------------------------------------------------------
// main GEMM + fused epilogue
// ---------------------------------------------------------------------------
__device__ __forceinline__ void stage_load(uint32_t st, int i0, int j0, int k0, int tid) {
    const int rr = tid >> 2;             // 0..63
    const int cb = (tid & 3) * 8;        // bf16 col within chunk
    const size_t kc = (size_t)k0 + cb;
#pragma unroll
    for (int s = 0; s < 4; s++) {
        const int row = rr + 64 * s;
        CP_ASYNC16(st + T_A + (uint32_t)(row * STRIDE + cb) * 2,
                   g_xb + (size_t)(i0 + row) * D_K + kc);
    }
#pragma unroll
    for (int s = 0; s < 2; s++) {
        const int row = rr + 64 * s;
        CP_ASYNC16(st + T_B + (uint32_t)(row * STRIDE + cb) * 2,
                   g_xb + (size_t)(j0 + row) * D_K + kc);
    }
}

__global__ __launch_bounds__(NTHR, 1) void snn_mma() {
    extern __shared__ __align__(16) char sm[];
    const uint32_t smb = smem_u32(sm);
    const int tid = threadIdx.x, wid = tid >> 5, lane = tid & 31;
    const int wM = wid >> 1, wN = wid & 1;      // 4x2 warp grid; warp tile 64x64

    // map linear block -> (I, J) with J >= 2I ; base(I) = I*(65-I)
    const int b = blockIdx.x;
    int I = 0;
    while (I < 31 && (I + 1) * (64 - I) <= b) I++;
    const int J = 2 * I + (b - I * (65 - I));
    const int i0 = I * BM, j0 = J * BN;
    const bool diag = (J <= 2 * I + 1);

    float* s_xnj  = (float*)(sm + NSTAGE * STAGE_SZ);
    int*   s_labj = (int*)(sm + NSTAGE * STAGE_SZ + 512);
    if (tid < BN) { s_xnj[tid] = g_xn[j0 + tid]; s_labj[tid] = g_lab[j0 + tid]; }

    // ldmatrix per-lane offsets
    const int arl  = lane & 15;
    const int asel = (lane >> 4) & 1;
    const int brl  = (lane & 7) | ((lane >> 4) << 3);
    const int bsel = (lane >> 3) & 1;
    uint32_t aob[4], bob[4];
#pragma unroll
    for (int mi = 0; mi < 4; mi++)
        aob[mi] = T_A + (uint32_t)((wM * 64 + mi * 16 + arl) * STRIDE + asel * 8) * 2;
#pragma unroll
    for (int bi = 0; bi < 4; bi++)
        bob[bi] = T_B + (uint32_t)((wN * 64 + bi * 16 + brl) * STRIDE + bsel * 8) * 2;

    float acc[4][8][4];
#pragma unroll
    for (int mi = 0; mi < 4; mi++)
#pragma unroll
        for (int ni = 0; ni < 8; ni++)
#pragma unroll
            for (int r = 0; r < 4; r++) acc[mi][ni][r] = 0.0f;

    stage_load(smb + 0 * STAGE_SZ, i0, j0, 0, tid);
    CP_COMMIT();
    stage_load(smb + 1 * STAGE_SZ, i0, j0, BK, tid);
    CP_COMMIT();

#pragma unroll 1
    for (int kt = 0; kt < ITERS; kt++) {
        CP_WAIT1();
        __syncthreads();
        if (kt + 2 < ITERS)
            stage_load(smb + ((kt + 2) % NSTAGE) * STAGE_SZ, i0, j0, (kt + 2) * BK, tid);
        CP_COMMIT();

        const uint32_t st = smb + (kt % NSTAGE) * STAGE_SZ;
#pragma unroll
        for (int ks = 0; ks < 2; ks++) {
            uint32_t a[4][4], bfr[4][4];
#pragma unroll
            for (int mi = 0; mi < 4; mi++) LDSM_X4(a[mi], st + aob[mi] + ks * 32);
#pragma unroll
            for (int bi = 0; bi < 4; bi++) LDSM_X4(bfr[bi], st + bob[bi] + ks * 32);
#pragma unroll
            for (int mi = 0; mi < 4; mi++)
#pragma unroll
                for (int ni = 0; ni < 8; ni++)
                    mma_bf16(acc[mi][ni], a[mi],
                             bfr[ni >> 1][(ni & 1) * 2], bfr[ni >> 1][(ni & 1) * 2 + 1]);
        }
    }

    // --- fused epilogue: rows always; cols only for strictly-upper tiles ---
    const float c0 = g_T * -1.4426950408889634f;
    float cd[8][2], cn[8][2];
#pragma unroll
    for (int ni = 0; ni < 8; ni++) { cd[ni][0] = cd[ni][1] = cn[ni][0] = cn[ni][1] = 0.0f; }

#pragma unroll
    for (int mi = 0; mi < 4; mi++) {
#pragma unroll
        for (int h = 0; h < 2; h++) {
            const int rowl = wM * 64 + mi * 16 + (lane >> 2) + h * 8;
            const int ig = i0 + rowl;
            const float xni = g_xn[ig];
            const int labi = g_lab[ig];
            float sd = 0.0f, sn = 0.0f;
#pragma unroll
            for (int ni = 0; ni < 8; ni++) {
#pragma unroll
                for (int e = 0; e < 2; e++) {
                    const int cl = wN * 64 + ni * 8 + (lane & 3) * 2 + e;
                    float dot = acc[mi][ni][h * 2 + e];
                    float d2 = fmaf(-2.0f, dot, xni + s_xnj[cl]);
                    d2 = fmaxf(d2, 0.0f);
                    float ev = fexp2_approx(c0 * fsqrt_approx(d2));
                    if (j0 + cl == ig) ev = 0.0f;
                    const bool same = (s_labj[cl] == labi);
                    sd += ev;
                    sn += same ? ev : 0.0f;
                    cd[ni][e] += ev;
                    cn[ni][e] += same ? ev : 0.0f;
                }
            }
            sd += __shfl_xor_sync(0xFFFFFFFFu, sd, 1);
            sd += __shfl_xor_sync(0xFFFFFFFFu, sd, 2);
            sn += __shfl_xor_sync(0xFFFFFFFFu, sn, 1);
            sn += __shfl_xor_sync(0xFFFFFFFFu, sn, 2);
            if ((lane & 3) == 0) {
                atomicAdd(&g_sden[ig], sd);
                atomicAdd(&g_snum[ig], sn);
            }
        }
    }

    if (!diag) {
        // column sums: reduce over the 8 row-lanes (xor 4,8,16), then lanes 0-3
        // own cols ni*8 + 2*lane + e.
#pragma unroll
        for (int ni = 0; ni < 8; ni++) {
#pragma unroll
            for (int e = 0; e < 2; e++) {
                float d = cd[ni][e], n = cn[ni][e];
#pragma unroll
                for (int off = 4; off < 32; off <<= 1) {
                    d += __shfl_xor_sync(0xFFFFFFFFu, d, off);
                    n += __shfl_xor_sync(0xFFFFFFFFu, n, off);
                }
                if (lane < 4) {
                    const int jg = j0 + wN * 64 + ni * 8 + lane * 2 + e;
                    atomicAdd(&g_sden[jg], d);
                    atomicAdd(&g_snum[jg], n);
                }
            }
        }
    }
}

// ---------------------------------------------------------------------------
// final reduction
// ---------------------------------------------------------------------------
__global__ void snn_final(float* __restrict__ out) {
    __shared__ float red[256];
    int tid = threadIdx.x;
    float local = 0.0f;
    for (int i = tid; i < B_N; i += 256) {
        float sn = g_snum[i], sd = g_sden[i];
        float num = (sn > 0.0f) ? logf(sn) : 0.0f;
        float den = logf(sd);
        local += num - den;
    }
    red[tid] = local;
    __syncthreads();
    for (int s = 128; s > 0; s >>= 1) { if (tid < s) red[tid] += red[tid + s]; __syncthreads(); }
    if (tid == 0) out[0] = -red[0] / (float)B_N;
}

// ---------------------------------------------------------------------------
extern "C" void kernel_launch(void* const* d_in, const int* in_sizes, int n_in,
                              void* d_out, int out_size)
{
    const float* x  = (const float*)d_in[0];
    const void*  y  = d_in[1];
    const void*  Tp = d_in[2];
    (void)in_sizes; (void)n_in; (void)out_size;

    cudaFuncSetAttribute(snn_mma, cudaFuncAttributeMaxDynamicSharedMemorySize, SMEM_TOTAL);

    snn_prep<<<1, 256>>>(Tp, (const unsigned*)y);
    snn_labels<<<B_N / 256, 256>>>(y);
    snn_rownorm<<<B_N / 8, 256>>>(x);
    snn_convert<<<(B_N * D_K / 8) / 256, 256>>>(x);
    snn_mma<<<NTILES, NTHR, SMEM_TOTAL>>>();
    snn_final<<<1, 256>>>((float*)d_out);
}

// round 7
// speedup vs baseline: 10.0183x; 1.0974x over previous
#include <cuda_runtime.h>
#include <cuda_bf16.h>
#include <cstdint>

// ---------------------------------------------------------------------------
// SNN loss via bf16 mma.sync Gram GEMM, single pass, symmetric schedule
// (tiles J >= 2I only; strictly-upper tiles accumulate rows AND columns).
// This round: 512 threads / 16 warps (warp tile 64x32, 64 acc regs) ->
// 4 warps per SMSP to cover HMMA latency (was 2).  rownorm+convert merged.
// ---------------------------------------------------------------------------

#define B_N   8192
#define D_K   1024
#define BM    256
#define BN    128
#define BK    32
#define ITERS (D_K / BK)    /* 32 */
#define NTHR  512
#define NSTAGE 3
#define STRIDE 40           /* padded smem row: 32 data + 8 pad bf16 = 80B */

#define T_A 0
#define T_B (BM * STRIDE * 2)                  /* 20480 */
#define STAGE_SZ ((BM + BN) * STRIDE * 2)      /* 30720 */
#define SMEM_TOTAL (NSTAGE * STAGE_SZ + 1024)  /* 93184 */
#define NTILES 1056                            /* sum_{I=0}^{31} (64-2I) */

__device__ float g_xn[B_N];
__device__ float g_snum[B_N];
__device__ float g_sden[B_N];
__device__ int   g_lab[B_N];
__device__ float g_T;
__device__ int   g_y_is64;
__device__ __nv_bfloat16 g_xb[(size_t)B_N * D_K];

// ------------------------------- helpers -----------------------------------
__device__ __forceinline__ uint32_t smem_u32(const void* p) {
    uint32_t a;
    asm("{ .reg .u64 t; cvta.to.shared.u64 t, %1; cvt.u32.u64 %0, t; }"
        : "=r"(a) : "l"(p));
    return a;
}
__device__ __forceinline__ float fsqrt_approx(float v) {
    float r; asm("sqrt.approx.f32 %0, %1;" : "=f"(r) : "f"(v)); return r;
}
__device__ __forceinline__ float fexp2_approx(float v) {
    float r; asm("ex2.approx.f32 %0, %1;" : "=f"(r) : "f"(v)); return r;
}

#define LDSM_X4(r, addr) \
    asm volatile("ldmatrix.sync.aligned.m8n8.x4.shared.b16 {%0,%1,%2,%3}, [%4];" \
        : "=r"((r)[0]), "=r"((r)[1]), "=r"((r)[2]), "=r"((r)[3]) : "r"(addr))

__device__ __forceinline__ void mma_bf16(float* c, const uint32_t* a,
                                         uint32_t b0, uint32_t b1) {
    asm volatile(
        "mma.sync.aligned.m16n8k16.row.col.f32.bf16.bf16.f32 "
        "{%0,%1,%2,%3}, {%4,%5,%6,%7}, {%8,%9}, {%0,%1,%2,%3};"
        : "+f"(c[0]), "+f"(c[1]), "+f"(c[2]), "+f"(c[3])
        : "r"(a[0]), "r"(a[1]), "r"(a[2]), "r"(a[3]), "r"(b0), "r"(b1));
}

#define CP_ASYNC16(dst, src) \
    asm volatile("cp.async.cg.shared.global [%0], [%1], 16;" \
                 :: "r"(dst), "l"(src) : "memory")
#define CP_COMMIT() asm volatile("cp.async.commit_group;" ::: "memory")
#define CP_WAIT1()  asm volatile("cp.async.wait_group 1;" ::: "memory")

// ---------------------------------------------------------------------------
// setup kernels
// ---------------------------------------------------------------------------
__global__ void snn_prep(const void* __restrict__ Tin, const unsigned* __restrict__ yw) {
    __shared__ unsigned s_or[256];
    const int tid = threadIdx.x;
    for (int i = tid; i < B_N; i += 256) { g_snum[i] = 0.0f; g_sden[i] = 0.0f; }
    unsigned acc = 0;
    for (int i = tid; i < B_N / 2; i += 256) acc |= yw[2 * i + 1];
    s_or[tid] = acc;
    __syncthreads();
    for (int s = 128; s > 0; s >>= 1) { if (tid < s) s_or[tid] |= s_or[tid + s]; __syncthreads(); }
    if (tid == 0) {
        g_y_is64 = (s_or[0] == 0u) ? 1 : 0;
        const unsigned* u = (const unsigned*)Tin;
        unsigned a = u[0];
        float T;
        if (a == 0x3F800000u) T = 1.0f;
        else if ((a & 0x7F800000u) >= 0x3F000000u && (a & 0x7F800000u) <= 0x43000000u)
            T = __uint_as_float(a);
        else if (a == 0u) {
            unsigned b = u[1];
            T = b ? (float)__longlong_as_double(((unsigned long long)b << 32) | a) : 0.0f;
        } else T = (float)(int)a;
        g_T = T;
    }
}

__global__ void snn_labels(const void* __restrict__ y) {
    int i = blockIdx.x * blockDim.x + threadIdx.x;
    if (i < B_N)
        g_lab[i] = g_y_is64 ? (int)((const long long*)y)[i] : ((const int*)y)[i];
}

// rownorm + bf16 convert fused: one warp per row, read x once
__global__ __launch_bounds__(256) void snn_rownorm_convert(const float* __restrict__ x) {
    int warp = threadIdx.x >> 5, lane = threadIdx.x & 31;
    int row  = blockIdx.x * 8 + warp;
    const float4* p = (const float4*)(x + (size_t)row * D_K);
    __nv_bfloat162* ob = (__nv_bfloat162*)(g_xb + (size_t)row * D_K);
    float s = 0.0f;
#pragma unroll
    for (int i = 0; i < 8; i++) {
        float4 v = p[i * 32 + lane];
        s += v.x * v.x + v.y * v.y + v.z * v.z + v.w * v.w;
        __nv_bfloat162 o0{__float2bfloat16(v.x), __float2bfloat16(v.y)};
        __nv_bfloat162 o1{__float2bfloat16(v.z), __float2bfloat16(v.w)};
        ob[(i * 32 + lane) * 2]     = o0;
        ob[(i * 32 + lane) * 2 + 1] = o1;
    }
#pragma unroll
    for (int off = 16; off > 0; off >>= 1) s += __shfl_down_sync(0xFFFFFFFFu, s, off);
    if (lane == 0) g_xn[row] = s;
}

// ---------------------------------------------------------------------------
// main GEMM + fused epilogue
// ---------------------------------------------------------------------------
__device__ __forceinline__ void stage_load(uint32_t st, int i0, int j0, int k0, int tid) {
    const int r0 = tid >> 2;             // 0..127
    const int cb = (tid & 3) * 8;        // bf16 col within chunk
    const size_t kc = (size_t)k0 + cb;
    // A: 256 rows, 2 chunks/thread
    CP_ASYNC16(st + T_A + (uint32_t)(r0 * STRIDE + cb) * 2,
               g_xb + (size_t)(i0 + r0) * D_K + kc);
    CP_ASYNC16(st + T_A + (uint32_t)((r0 + 128) * STRIDE + cb) * 2,
               g_xb + (size_t)(i0 + r0 + 128) * D_K + kc);
    // B: 128 rows, 1 chunk/thread
    CP_ASYNC16(st + T_B + (uint32_t)(r0 * STRIDE + cb) * 2,
               g_xb + (size_t)(j0 + r0) * D_K + kc);
}

__global__ __launch_bounds__(NTHR, 1) void snn_mma() {
    extern __shared__ __align__(16) char sm[];
    const uint32_t smb = smem_u32(sm);
    const int tid = threadIdx.x, wid = tid >> 5, lane = tid & 31;
    const int wM = wid >> 2, wN = wid & 3;      // 4x4 warp grid; warp tile 64x32

    // map linear block -> (I, J) with J >= 2I ; base(I) = I*(65-I)
    const int b = blockIdx.x;
    int I = 0;
    while (I < 31 && (I + 1) * (64 - I) <= b) I++;
    const int J = 2 * I + (b - I * (65 - I));
    const int i0 = I * BM, j0 = J * BN;
    const bool diag = (J <= 2 * I + 1);

    float* s_xnj  = (float*)(sm + NSTAGE * STAGE_SZ);
    int*   s_labj = (int*)(sm + NSTAGE * STAGE_SZ + 512);
    if (tid < BN) { s_xnj[tid] = g_xn[j0 + tid]; s_labj[tid] = g_lab[j0 + tid]; }

    // ldmatrix per-lane offsets (round-4 validated mapping)
    const int arl  = lane & 15;
    const int asel = (lane >> 4) & 1;
    const int brl  = (lane & 7) | ((lane >> 4) << 3);
    const int bsel = (lane >> 3) & 1;
    uint32_t aob[4], bob[2];
#pragma unroll
    for (int mi = 0; mi < 4; mi++)
        aob[mi] = T_A + (uint32_t)((wM * 64 + mi * 16 + arl) * STRIDE + asel * 8) * 2;
#pragma unroll
    for (int bi = 0; bi < 2; bi++)
        bob[bi] = T_B + (uint32_t)((wN * 32 + bi * 16 + brl) * STRIDE + bsel * 8) * 2;

    float acc[4][4][4];
#pragma unroll
    for (int mi = 0; mi < 4; mi++)
#pragma unroll
        for (int ni = 0; ni < 4; ni++)
#pragma unroll
            for (int r = 0; r < 4; r++) acc[mi][ni][r] = 0.0f;

    stage_load(smb + 0 * STAGE_SZ, i0, j0, 0, tid);
    CP_COMMIT();
    stage_load(smb + 1 * STAGE_SZ, i0, j0, BK, tid);
    CP_COMMIT();

#pragma unroll 1
    for (int kt = 0; kt < ITERS; kt++) {
        CP_WAIT1();
        __syncthreads();
        if (kt + 2 < ITERS)
            stage_load(smb + ((kt + 2) % NSTAGE) * STAGE_SZ, i0, j0, (kt + 2) * BK, tid);
        CP_COMMIT();

        const uint32_t st = smb + (kt % NSTAGE) * STAGE_SZ;
#pragma unroll
        for (int ks = 0; ks < 2; ks++) {
            uint32_t a[4][4], bf[2][4];
#pragma unroll
            for (int mi = 0; mi < 4; mi++) LDSM_X4(a[mi], st + aob[mi] + ks * 32);
#pragma unroll
            for (int bi = 0; bi < 2; bi++) LDSM_X4(bf[bi], st + bob[bi] + ks * 32);
#pragma unroll
            for (int mi = 0; mi < 4; mi++)
#pragma unroll
                for (int ni = 0; ni < 4; ni++)
                    mma_bf16(acc[mi][ni], a[mi],
                             bf[ni >> 1][(ni & 1) * 2], bf[ni >> 1][(ni & 1) * 2 + 1]);
        }
    }

    // --- fused epilogue: rows always; cols only for strictly-upper tiles ---
    const float c0 = g_T * -1.4426950408889634f;
    float cd[4][2], cn[4][2];
#pragma unroll
    for (int ni = 0; ni < 4; ni++) { cd[ni][0] = cd[ni][1] = cn[ni][0] = cn[ni][1] = 0.0f; }

#pragma unroll
    for (int mi = 0; mi < 4; mi++) {
#pragma unroll
        for (int h = 0; h < 2; h++) {
            const int rowl = wM * 64 + mi * 16 + (lane >> 2) + h * 8;
            const int ig = i0 + rowl;
            const float xni = g_xn[ig];
            const int labi = g_lab[ig];
            float sd = 0.0f, sn = 0.0f;
#pragma unroll
            for (int ni = 0; ni < 4; ni++) {
#pragma unroll
                for (int e = 0; e < 2; e++) {
                    const int cl = wN * 32 + ni * 8 + (lane & 3) * 2 + e;
                    float dot = acc[mi][ni][h * 2 + e];
                    float d2 = fmaf(-2.0f, dot, xni + s_xnj[cl]);
                    d2 = fmaxf(d2, 0.0f);
                    float ev = fexp2_approx(c0 * fsqrt_approx(d2));
                    if (j0 + cl == ig) ev = 0.0f;
                    const bool same = (s_labj[cl] == labi);
                    sd += ev;
                    sn += same ? ev : 0.0f;
                    cd[ni][e] += ev;
                    cn[ni][e] += same ? ev : 0.0f;
                }
            }
            sd += __shfl_xor_sync(0xFFFFFFFFu, sd, 1);
            sd += __shfl_xor_sync(0xFFFFFFFFu, sd, 2);
            sn += __shfl_xor_sync(0xFFFFFFFFu, sn, 1);
            sn += __shfl_xor_sync(0xFFFFFFFFu, sn, 2);
            if ((lane & 3) == 0) {
                atomicAdd(&g_sden[ig], sd);
                atomicAdd(&g_snum[ig], sn);
            }
        }
    }

    if (!diag) {
        // column sums: reduce over the 8 row-lanes (xor 4,8,16); lanes 0-3 own cols
#pragma unroll
        for (int ni = 0; ni < 4; ni++) {
#pragma unroll
            for (int e = 0; e < 2; e++) {
                float d = cd[ni][e], n = cn[ni][e];
#pragma unroll
                for (int off = 4; off < 32; off <<= 1) {
                    d += __shfl_xor_sync(0xFFFFFFFFu, d, off);
                    n += __shfl_xor_sync(0xFFFFFFFFu, n, off);
                }
                if (lane < 4) {
                    const int jg = j0 + wN * 32 + ni * 8 + lane * 2 + e;
                    atomicAdd(&g_sden[jg], d);
                    atomicAdd(&g_snum[jg], n);
                }
            }
        }
    }
}

// ---------------------------------------------------------------------------
// final reduction
// ---------------------------------------------------------------------------
__global__ void snn_final(float* __restrict__ out) {
    __shared__ float red[256];
    int tid = threadIdx.x;
    float local = 0.0f;
    for (int i = tid; i < B_N; i += 256) {
        float sn = g_snum[i], sd = g_sden[i];
        float num = (sn > 0.0f) ? logf(sn) : 0.0f;
        float den = logf(sd);
        local += num - den;
    }
    red[tid] = local;
    __syncthreads();
    for (int s = 128; s > 0; s >>= 1) { if (tid < s) red[tid] += red[tid + s]; __syncthreads(); }
    if (tid == 0) out[0] = -red[0] / (float)B_N;
}

// ---------------------------------------------------------------------------
extern "C" void kernel_launch(void* const* d_in, const int* in_sizes, int n_in,
                              void* d_out, int out_size)
{
    const float* x  = (const float*)d_in[0];
    const void*  y  = d_in[1];
    const void*  Tp = d_in[2];
    (void)in_sizes; (void)n_in; (void)out_size;

    cudaFuncSetAttribute(snn_mma, cudaFuncAttributeMaxDynamicSharedMemorySize, SMEM_TOTAL);

    snn_prep<<<1, 256>>>(Tp, (const unsigned*)y);
    snn_labels<<<B_N / 256, 256>>>(y);
    snn_rownorm_convert<<<B_N / 8, 256>>>(x);
    snn_mma<<<NTILES, NTHR, SMEM_TOTAL>>>();
    snn_final<<<1, 256>>>((float*)d_out);
}

// round 8
// speedup vs baseline: 12.4897x; 1.2467x over previous
#include <cuda_runtime.h>
#include <cuda_bf16.h>
#include <cstdint>

// ---------------------------------------------------------------------------
// SNN loss via bf16 mma.sync Gram GEMM, single pass, symmetric schedule.
// Round 8: 128x128 CTA tiles, 2 CTAs/SM (cross-CTA barrier overlap), BK=64
// (half the barriers). Tiles (I,J), J>=I: diagonal tiles row-accumulate only;
// strictly-upper tiles accumulate rows AND mirrored columns.
// ---------------------------------------------------------------------------

#define B_N   8192
#define D_K   1024
#define BM    128
#define BN    128
#define BK    64
#define ITERS (D_K / BK)    /* 16 */
#define NTHR  256
#define NSTAGE 3
#define STRIDE 72           /* padded smem row: 64 data + 8 pad bf16 = 144B */

#define T_A 0
#define T_B (BM * STRIDE * 2)                  /* 18432 */
#define STAGE_SZ ((BM + BN) * STRIDE * 2)      /* 36864 */
#define SMEM_TOTAL (NSTAGE * STAGE_SZ + 1024)  /* 111616 */
#define NTILES 2080                            /* 64*65/2 */

__device__ float g_xn[B_N];
__device__ float g_snum[B_N];
__device__ float g_sden[B_N];
__device__ int   g_lab[B_N];
__device__ float g_T;
__device__ int   g_y_is64;
__device__ __nv_bfloat16 g_xb[(size_t)B_N * D_K];

// ------------------------------- helpers -----------------------------------
__device__ __forceinline__ uint32_t smem_u32(const void* p) {
    uint32_t a;
    asm("{ .reg .u64 t; cvta.to.shared.u64 t, %1; cvt.u32.u64 %0, t; }"
        : "=r"(a) : "l"(p));
    return a;
}
__device__ __forceinline__ float fsqrt_approx(float v) {
    float r; asm("sqrt.approx.f32 %0, %1;" : "=f"(r) : "f"(v)); return r;
}
__device__ __forceinline__ float fexp2_approx(float v) {
    float r; asm("ex2.approx.f32 %0, %1;" : "=f"(r) : "f"(v)); return r;
}

#define LDSM_X4(r, addr) \
    asm volatile("ldmatrix.sync.aligned.m8n8.x4.shared.b16 {%0,%1,%2,%3}, [%4];" \
        : "=r"((r)[0]), "=r"((r)[1]), "=r"((r)[2]), "=r"((r)[3]) : "r"(addr))

__device__ __forceinline__ void mma_bf16(float* c, const uint32_t* a,
                                         uint32_t b0, uint32_t b1) {
    asm volatile(
        "mma.sync.aligned.m16n8k16.row.col.f32.bf16.bf16.f32 "
        "{%0,%1,%2,%3}, {%4,%5,%6,%7}, {%8,%9}, {%0,%1,%2,%3};"
        : "+f"(c[0]), "+f"(c[1]), "+f"(c[2]), "+f"(c[3])
        : "r"(a[0]), "r"(a[1]), "r"(a[2]), "r"(a[3]), "r"(b0), "r"(b1));
}

#define CP_ASYNC16(dst, src) \
    asm volatile("cp.async.cg.shared.global [%0], [%1], 16;" \
                 :: "r"(dst), "l"(src) : "memory")
#define CP_COMMIT() asm volatile("cp.async.commit_group;" ::: "memory")
#define CP_WAIT1()  asm volatile("cp.async.wait_group 1;" ::: "memory")

// ---------------------------------------------------------------------------
// setup kernels
// ---------------------------------------------------------------------------
__global__ void snn_prep(const void* __restrict__ Tin, const unsigned* __restrict__ yw) {
    __shared__ unsigned s_or[256];
    const int tid = threadIdx.x;
    for (int i = tid; i < B_N; i += 256) { g_snum[i] = 0.0f; g_sden[i] = 0.0f; }
    unsigned acc = 0;
    for (int i = tid; i < B_N / 2; i += 256) acc |= yw[2 * i + 1];
    s_or[tid] = acc;
    __syncthreads();
    for (int s = 128; s > 0; s >>= 1) { if (tid < s) s_or[tid] |= s_or[tid + s]; __syncthreads(); }
    if (tid == 0) {
        g_y_is64 = (s_or[0] == 0u) ? 1 : 0;
        const unsigned* u = (const unsigned*)Tin;
        unsigned a = u[0];
        float T;
        if (a == 0x3F800000u) T = 1.0f;
        else if ((a & 0x7F800000u) >= 0x3F000000u && (a & 0x7F800000u) <= 0x43000000u)
            T = __uint_as_float(a);
        else if (a == 0u) {
            unsigned b = u[1];
            T = b ? (float)__longlong_as_double(((unsigned long long)b << 32) | a) : 0.0f;
        } else T = (float)(int)a;
        g_T = T;
    }
}

__global__ void snn_labels(const void* __restrict__ y) {
    int i = blockIdx.x * blockDim.x + threadIdx.x;
    if (i < B_N)
        g_lab[i] = g_y_is64 ? (int)((const long long*)y)[i] : ((const int*)y)[i];
}

// rownorm + bf16 convert fused: one warp per row, read x once
__global__ __launch_bounds__(256) void snn_rownorm_convert(const float* __restrict__ x) {
    int warp = threadIdx.x >> 5, lane = threadIdx.x & 31;
    int row  = blockIdx.x * 8 + warp;
    const float4* p = (const float4*)(x + (size_t)row * D_K);
    __nv_bfloat162* ob = (__nv_bfloat162*)(g_xb + (size_t)row * D_K);
    float s = 0.0f;
#pragma unroll
    for (int i = 0; i < 8; i++) {
        float4 v = p[i * 32 + lane];
        s += v.x * v.x + v.y * v.y + v.z * v.z + v.w * v.w;
        __nv_bfloat162 o0{__float2bfloat16(v.x), __float2bfloat16(v.y)};
        __nv_bfloat162 o1{__float2bfloat16(v.z), __float2bfloat16(v.w)};
        ob[(i * 32 + lane) * 2]     = o0;
        ob[(i * 32 + lane) * 2 + 1] = o1;
    }
#pragma unroll
    for (int off = 16; off > 0; off >>= 1) s += __shfl_down_sync(0xFFFFFFFFu, s, off);
    if (lane == 0) g_xn[row] = s;
}

// ---------------------------------------------------------------------------
// main GEMM + fused epilogue
// ---------------------------------------------------------------------------
__device__ __forceinline__ void stage_load(uint32_t st, int i0, int j0, int k0, int tid) {
    const int rr = tid >> 3;             // 0..31
    const int cb = (tid & 7) * 8;        // bf16 col within 64-wide chunk
    const size_t kc = (size_t)k0 + cb;
    const uint32_t so = (uint32_t)(rr * STRIDE + cb) * 2;
#pragma unroll
    for (int s = 0; s < 4; s++) {        // A rows 0..127
        CP_ASYNC16(st + T_A + so + (uint32_t)(32 * s * STRIDE) * 2,
                   g_xb + (size_t)(i0 + rr + 32 * s) * D_K + kc);
    }
#pragma unroll
    for (int s = 0; s < 4; s++) {        // B rows 0..127
        CP_ASYNC16(st + T_B + so + (uint32_t)(32 * s * STRIDE) * 2,
                   g_xb + (size_t)(j0 + rr + 32 * s) * D_K + kc);
    }
}

__global__ __launch_bounds__(NTHR, 2) void snn_mma() {
    extern __shared__ __align__(16) char sm[];
    const uint32_t smb = smem_u32(sm);
    const int tid = threadIdx.x, wid = tid >> 5, lane = tid & 31;
    const int wM = wid >> 1, wN = wid & 1;      // 4x2 warp grid; warp tile 32x64

    // map linear block -> (I, J) with J >= I ; base(I) = 64I - I(I-1)/2
    const int b = blockIdx.x;
    int I = 0;
    while (I < 63 && (64 * (I + 1) - ((I + 1) * I) / 2) <= b) I++;
    const int J = I + (b - (64 * I - (I * (I - 1)) / 2));
    const int i0 = I * BM, j0 = J * BN;
    const bool diag = (I == J);

    float* s_xnj  = (float*)(sm + NSTAGE * STAGE_SZ);
    int*   s_labj = (int*)(sm + NSTAGE * STAGE_SZ + 512);
    if (tid < BN) { s_xnj[tid] = g_xn[j0 + tid]; s_labj[tid] = g_lab[j0 + tid]; }

    // ldmatrix per-lane offsets
    const int arl  = lane & 15;
    const int asel = (lane >> 4) & 1;
    const int brl  = (lane & 7) | ((lane >> 4) << 3);
    const int bsel = (lane >> 3) & 1;
    uint32_t aob[2], bob[4];
#pragma unroll
    for (int mi = 0; mi < 2; mi++)
        aob[mi] = T_A + (uint32_t)((wM * 32 + mi * 16 + arl) * STRIDE + asel * 8) * 2;
#pragma unroll
    for (int bi = 0; bi < 4; bi++)
        bob[bi] = T_B + (uint32_t)((wN * 64 + bi * 16 + brl) * STRIDE + bsel * 8) * 2;

    float acc[2][8][4];
#pragma unroll
    for (int mi = 0; mi < 2; mi++)
#pragma unroll
        for (int ni = 0; ni < 8; ni++)
#pragma unroll
            for (int r = 0; r < 4; r++) acc[mi][ni][r] = 0.0f;

    stage_load(smb + 0 * STAGE_SZ, i0, j0, 0, tid);
    CP_COMMIT();
    stage_load(smb + 1 * STAGE_SZ, i0, j0, BK, tid);
    CP_COMMIT();

#pragma unroll 1
    for (int kt = 0; kt < ITERS; kt++) {
        CP_WAIT1();
        __syncthreads();
        if (kt + 2 < ITERS)
            stage_load(smb + ((kt + 2) % NSTAGE) * STAGE_SZ, i0, j0, (kt + 2) * BK, tid);
        CP_COMMIT();

        const uint32_t st = smb + (kt % NSTAGE) * STAGE_SZ;
#pragma unroll
        for (int ks = 0; ks < 4; ks++) {
            uint32_t a[2][4], bf[4][4];
#pragma unroll
            for (int mi = 0; mi < 2; mi++) LDSM_X4(a[mi], st + aob[mi] + ks * 32);
#pragma unroll
            for (int bi = 0; bi < 4; bi++) LDSM_X4(bf[bi], st + bob[bi] + ks * 32);
#pragma unroll
            for (int mi = 0; mi < 2; mi++)
#pragma unroll
                for (int ni = 0; ni < 8; ni++)
                    mma_bf16(acc[mi][ni], a[mi],
                             bf[ni >> 1][(ni & 1) * 2], bf[ni >> 1][(ni & 1) * 2 + 1]);
        }
    }

    // --- fused epilogue: rows always; cols only for strictly-upper tiles ---
    const float c0 = g_T * -1.4426950408889634f;
    float cd[8][2], cn[8][2];
#pragma unroll
    for (int ni = 0; ni < 8; ni++) { cd[ni][0] = cd[ni][1] = cn[ni][0] = cn[ni][1] = 0.0f; }

#pragma unroll
    for (int mi = 0; mi < 2; mi++) {
#pragma unroll
        for (int h = 0; h < 2; h++) {
            const int rowl = wM * 32 + mi * 16 + (lane >> 2) + h * 8;
            const int ig = i0 + rowl;
            const float xni = g_xn[ig];
            const int labi = g_lab[ig];
            float sd = 0.0f, sn = 0.0f;
#pragma unroll
            for (int ni = 0; ni < 8; ni++) {
#pragma unroll
                for (int e = 0; e < 2; e++) {
                    const int cl = wN * 64 + ni * 8 + (lane & 3) * 2 + e;
                    float dot = acc[mi][ni][h * 2 + e];
                    float d2 = fmaf(-2.0f, dot, xni + s_xnj[cl]);
                    d2 = fmaxf(d2, 0.0f);
                    float ev = fexp2_approx(c0 * fsqrt_approx(d2));
                    if (j0 + cl == ig) ev = 0.0f;
                    const bool same = (s_labj[cl] == labi);
                    sd += ev;
                    sn += same ? ev : 0.0f;
                    cd[ni][e] += ev;
                    cn[ni][e] += same ? ev : 0.0f;
                }
            }
            sd += __shfl_xor_sync(0xFFFFFFFFu, sd, 1);
            sd += __shfl_xor_sync(0xFFFFFFFFu, sd, 2);
            sn += __shfl_xor_sync(0xFFFFFFFFu, sn, 1);
            sn += __shfl_xor_sync(0xFFFFFFFFu, sn, 2);
            if ((lane & 3) == 0) {
                atomicAdd(&g_sden[ig], sd);
                atomicAdd(&g_snum[ig], sn);
            }
        }
    }

    if (!diag) {
        // column sums: reduce over the 8 row-lane groups (xor 4,8,16); lanes 0-3 own cols
#pragma unroll
        for (int ni = 0; ni < 8; ni++) {
#pragma unroll
            for (int e = 0; e < 2; e++) {
                float d = cd[ni][e], n = cn[ni][e];
#pragma unroll
                for (int off = 4; off < 32; off <<= 1) {
                    d += __shfl_xor_sync(0xFFFFFFFFu, d, off);
                    n += __shfl_xor_sync(0xFFFFFFFFu, n, off);
                }
                if (lane < 4) {
                    const int jg = j0 + wN * 64 + ni * 8 + lane * 2 + e;
                    atomicAdd(&g_sden[jg], d);
                    atomicAdd(&g_snum[jg], n);
                }
            }
        }
    }
}

// ---------------------------------------------------------------------------
// final reduction
// ---------------------------------------------------------------------------
__global__ void snn_final(float* __restrict__ out) {
    __shared__ float red[256];
    int tid = threadIdx.x;
    float local = 0.0f;
    for (int i = tid; i < B_N; i += 256) {
        float sn = g_snum[i], sd = g_sden[i];
        float num = (sn > 0.0f) ? logf(sn) : 0.0f;
        float den = logf(sd);
        local += num - den;
    }
    red[tid] = local;
    __syncthreads();
    for (int s = 128; s > 0; s >>= 1) { if (tid < s) red[tid] += red[tid + s]; __syncthreads(); }
    if (tid == 0) out[0] = -red[0] / (float)B_N;
}

// ---------------------------------------------------------------------------
extern "C" void kernel_launch(void* const* d_in, const int* in_sizes, int n_in,
                              void* d_out, int out_size)
{
    const float* x  = (const float*)d_in[0];
    const void*  y  = d_in[1];
    const void*  Tp = d_in[2];
    (void)in_sizes; (void)n_in; (void)out_size;

    cudaFuncSetAttribute(snn_mma, cudaFuncAttributeMaxDynamicSharedMemorySize, SMEM_TOTAL);

    snn_prep<<<1, 256>>>(Tp, (const unsigned*)y);
    snn_labels<<<B_N / 256, 256>>>(y);
    snn_rownorm_convert<<<B_N / 8, 256>>>(x);
    snn_mma<<<NTILES, NTHR, SMEM_TOTAL>>>();
    snn_final<<<1, 256>>>((float*)d_out);
}